// round 8
// baseline (speedup 1.0000x reference)
#include <cuda_runtime.h>
#include <cuda_fp16.h>
#include <math.h>
#include <stdint.h>

#define M_BATCH 2048
#define N_OUT   4096
#define K_IN    4096

// Persistent fp16 operands (module-load allocations; no runtime alloc).
__device__ __half g_xh[(size_t)M_BATCH * K_IN];   // fp16(x)
__device__ __half g_wh[(size_t)N_OUT * K_IN];     // fp16(Wn)

// ---------------------------------------------------------------------------
__device__ __forceinline__ uint32_t smem_u32(const void* p) {
    uint32_t a;
    asm("{ .reg .u64 t; cvta.to.shared.u64 t, %1; cvt.u32.u64 %0, t; }"
        : "=r"(a) : "l"(p));
    return a;
}
__device__ __forceinline__ void cp16(uint32_t s, const void* g) {
    asm volatile("cp.async.cg.shared.global [%0], [%1], 16;" :: "r"(s), "l"(g));
}
#define CP_COMMIT() asm volatile("cp.async.commit_group;" ::: "memory")
#define CP_WAIT2()  asm volatile("cp.async.wait_group 2;" ::: "memory")

#define LDM4(d, addr)                                                         \
    asm volatile("ldmatrix.sync.aligned.m8n8.x4.shared.b16 {%0,%1,%2,%3}, [%4];" \
        : "=r"((d)[0]), "=r"((d)[1]), "=r"((d)[2]), "=r"((d)[3]) : "r"(addr))

#define MMAF16(c, a, b0, b1)                                                  \
    asm volatile("mma.sync.aligned.m16n8k16.row.col.f32.f16.f16.f32 "         \
        "{%0,%1,%2,%3}, {%4,%5,%6,%7}, {%8,%9}, {%0,%1,%2,%3};"               \
        : "+f"((c)[0]), "+f"((c)[1]), "+f"((c)[2]), "+f"((c)[3])              \
        : "r"((a)[0]), "r"((a)[1]), "r"((a)[2]), "r"((a)[3]), "r"(b0), "r"(b1))

// ---------------------------------------------------------------------------
// Merged prep: blocks [0,4096) do W rows; blocks [4096,12288) do x slices.
// Runs as ONE launch so both memory streams overlap.
// ---------------------------------------------------------------------------
__global__ void prep_all(const float* __restrict__ x,
                         const float* __restrict__ W,
                         const float* __restrict__ wls,
                         float* __restrict__ jac_out) {
    extern __shared__ float sh[];    // [4096] row cache + [256] reduction
    if (blockIdx.x < 4096) {
        const int o = blockIdx.x;
        const int br = o >> 5;
        const int ncols = (br + 1) << 5;
        const int dstart = br << 5;
        const int kmax_tile = ((o >> 7) + 1) << 7;

        float* row = sh;
        float* red = sh + 4096;

        const float* wrow = W + (size_t)o * K_IN;
        __half* wh = g_wh + (size_t)o * K_IN;

        float ss = 0.f;
        for (int i = threadIdx.x; i < ncols; i += blockDim.x) {
            float w = wrow[i];
            float wm = (i >= dstart) ? expf(w) : w;
            row[i] = w;
            ss += wm * wm;
        }
        red[threadIdx.x] = ss;
        __syncthreads();
        #pragma unroll
        for (int s = 128; s > 0; s >>= 1) {
            if (threadIdx.x < s) red[threadIdx.x] += red[threadIdx.x + s];
            __syncthreads();
        }
        const float norm   = sqrtf(red[0]);
        const float lscale = wls[o];
        const float coef   = expf(lscale) / norm;
        const float logn   = logf(norm);

        for (int i = threadIdx.x; i < ncols; i += blockDim.x) {
            float w = row[i];
            float wm = (i >= dstart) ? expf(w) : w;
            wh[i] = __float2half_rn(coef * wm);
            if (i >= dstart)
                jac_out[(size_t)o * 32 + (i - dstart)] = lscale + w - logn;
        }
        const __half z = __float2half_rn(0.f);
        for (int i = ncols + threadIdx.x; i < kmax_tile; i += blockDim.x)
            wh[i] = z;
    } else {
        size_t i = ((size_t)(blockIdx.x - 4096) * blockDim.x + threadIdx.x) * 4;
        float4 v = *(const float4*)(x + i);
        __half h0 = __float2half_rn(v.x), h1 = __float2half_rn(v.y);
        __half h2 = __float2half_rn(v.z), h3 = __float2half_rn(v.w);
        *(__half2*)(&g_xh[i])     = __halves2half2(h0, h1);
        *(__half2*)(&g_xh[i + 2]) = __halves2half2(h2, h3);
    }
}

// ---------------------------------------------------------------------------
// fp16 GEMM: y = fp16(x) @ fp16(Wn)^T + bias.
// CTA tile 256x128, 8 warps (4m x 2n => 64x64 per warp), BK=64,
// 4-stage cp.async pipeline (192 KB smem), one __syncthreads per chunk.
// Triangular: Kmax = 128*(nt+1); heaviest tiles first. Grid 256 = 32nt x 8mt.
// Stage (48 KB): A @0 (256x64), B @32K (128x64). Swizzle: 16B-chunk ^= (row&7).
// ---------------------------------------------------------------------------
#define STAGE 49152
#define NSTAGE 4
#define SMEM_TOTAL (NSTAGE * STAGE)

__global__ __launch_bounds__(256, 1)
void gemm_mma(const float* __restrict__ bias, float* __restrict__ y) {
    extern __shared__ __align__(1024) char smem[];
    const uint32_t sb = smem_u32(smem);

    const int tid  = threadIdx.x;
    const int wid  = tid >> 5;
    const int lane = tid & 31;
    const int wm = wid >> 1;          // 0..3 (m)
    const int wn = wid & 1;           // 0..1 (n)

    const int bid = blockIdx.x;
    const int nt = 31 - (bid >> 3);   // heaviest n-tiles first
    const int mt = bid & 7;
    const int n0 = nt << 7;
    const int m0 = mt << 8;
    const int NC = (nt + 1) << 1;     // K chunks of 64

    const __half* gA = g_xh + (size_t)m0 * K_IN;
    const __half* gB = g_wh + (size_t)n0 * K_IN;

    float acc[4][8][4];
    #pragma unroll
    for (int i = 0; i < 4; i++)
        #pragma unroll
        for (int j = 0; j < 8; j++)
            #pragma unroll
            for (int k = 0; k < 4; k++) acc[i][j][k] = 0.f;

    auto load_stage = [&](int s, int c) {
        const uint32_t base = sb + s * STAGE;
        const int k0 = c << 6;
        #pragma unroll
        for (int i = 0; i < 8; i++) {              // A: 256 rows x 8 chunks
            const int idx = tid + (i << 8);
            const int r = idx >> 3;
            const int ch = idx & 7;
            const size_t go = (size_t)r * K_IN + k0 + (ch << 3);
            const uint32_t so = (uint32_t)((r << 7) | ((ch ^ (r & 7)) << 4));
            cp16(base + so, gA + go);
        }
        #pragma unroll
        for (int i = 0; i < 4; i++) {              // B: 128 rows x 8 chunks
            const int idx = tid + (i << 8);
            const int r = idx >> 3;
            const int ch = idx & 7;
            const size_t go = (size_t)r * K_IN + k0 + (ch << 3);
            const uint32_t so = (uint32_t)((r << 7) | ((ch ^ (r & 7)) << 4));
            cp16(base + 32768 + so, gB + go);
        }
    };

    // Prologue: 3 committed groups (empty beyond NC).
    #pragma unroll
    for (int p = 0; p < 3; p++) {
        if (p < NC) load_stage(p, p);
        CP_COMMIT();
    }

    for (int c = 0; c < NC; ++c) {
        CP_WAIT2();                        // chunk c's group complete
        __syncthreads();                   // all warps done with chunk c-1
        if (c + 3 < NC) load_stage((c + 3) & 3, c + 3);
        CP_COMMIT();                       // empty group in the tail

        const uint32_t base = sb + (c & 3) * STAGE;
        #pragma unroll
        for (int ks = 0; ks < 4; ks++) {
            uint32_t ah[4][4];
            #pragma unroll
            for (int mf = 0; mf < 4; mf++) {
                const int row = (wm << 6) + (mf << 4) + (lane & 15);
                const int ch = ((ks << 1) + (lane >> 4)) ^ (row & 7);
                LDM4(ah[mf], base + (row << 7) + (ch << 4));
            }
            #pragma unroll
            for (int ng = 0; ng < 4; ng++) {
                const int n = (wn << 6) + (ng << 4) + ((lane >> 4) << 3) + (lane & 7);
                const int ch = ((ks << 1) + ((lane >> 3) & 1)) ^ (n & 7);
                uint32_t bh[4];
                LDM4(bh, base + 32768 + (n << 7) + (ch << 4));
                #pragma unroll
                for (int mf = 0; mf < 4; mf++)
                    #pragma unroll
                    for (int h = 0; h < 2; h++)
                        MMAF16(acc[mf][(ng << 1) + h], ah[mf], bh[2 * h], bh[2 * h + 1]);
            }
        }
    }

    // Epilogue
    #pragma unroll
    for (int mf = 0; mf < 4; mf++) {
        const int r = m0 + (wm << 6) + (mf << 4) + (lane >> 2);
        #pragma unroll
        for (int nf = 0; nf < 8; nf++) {
            const int cc = n0 + (wn << 6) + (nf << 3) + ((lane & 3) << 1);
            const float b0 = __ldg(bias + cc);
            const float b1 = __ldg(bias + cc + 1);
            float2 v0 = { acc[mf][nf][0] + b0, acc[mf][nf][1] + b1 };
            float2 v1 = { acc[mf][nf][2] + b0, acc[mf][nf][3] + b1 };
            *(float2*)(y + (size_t)r * N_OUT + cc)       = v0;
            *(float2*)(y + (size_t)(r + 8) * N_OUT + cc) = v1;
        }
    }
}

// ---------------------------------------------------------------------------
extern "C" void kernel_launch(void* const* d_in, const int* in_sizes, int n_in,
                              void* d_out, int out_size) {
    const float* x    = (const float*)d_in[0];
    const float* W    = (const float*)d_in[1];
    const float* bias = (const float*)d_in[2];
    const float* wls  = (const float*)d_in[3];
    // masks (d_in[4], d_in[5]) deterministic; never read.

    float* y   = (float*)d_out;
    float* jac = y + (size_t)M_BATCH * N_OUT;

    cudaFuncSetAttribute(gemm_mma, cudaFuncAttributeMaxDynamicSharedMemorySize,
                         SMEM_TOTAL);

    prep_all<<<12288, 256, (4096 + 256) * sizeof(float)>>>(x, W, wls, jac);
    gemm_mma<<<256, 256, SMEM_TOTAL>>>(bias, y);
}

// round 9
// speedup vs baseline: 1.0354x; 1.0354x over previous
#include <cuda_runtime.h>
#include <cuda_fp16.h>
#include <math.h>
#include <stdint.h>

#define M_BATCH 2048
#define N_OUT   4096
#define K_IN    4096

// Persistent fp16 operands (module-load allocations; no runtime alloc).
__device__ __half g_xh[(size_t)M_BATCH * K_IN];   // fp16(x)
__device__ __half g_wh[(size_t)N_OUT * K_IN];     // fp16(Wn)

// ---------------------------------------------------------------------------
__device__ __forceinline__ uint32_t smem_u32(const void* p) {
    uint32_t a;
    asm("{ .reg .u64 t; cvta.to.shared.u64 t, %1; cvt.u32.u64 %0, t; }"
        : "=r"(a) : "l"(p));
    return a;
}
__device__ __forceinline__ void cp16(uint32_t s, const void* g) {
    asm volatile("cp.async.cg.shared.global [%0], [%1], 16;" :: "r"(s), "l"(g));
}
#define CP_COMMIT() asm volatile("cp.async.commit_group;" ::: "memory")
#define CP_WAIT1()  asm volatile("cp.async.wait_group 1;" ::: "memory")

#define LDM4(d, addr)                                                         \
    asm volatile("ldmatrix.sync.aligned.m8n8.x4.shared.b16 {%0,%1,%2,%3}, [%4];" \
        : "=r"((d)[0]), "=r"((d)[1]), "=r"((d)[2]), "=r"((d)[3]) : "r"(addr))

#define MMAF16(c, a, b0, b1)                                                  \
    asm volatile("mma.sync.aligned.m16n8k16.row.col.f32.f16.f16.f32 "         \
        "{%0,%1,%2,%3}, {%4,%5,%6,%7}, {%8,%9}, {%0,%1,%2,%3};"               \
        : "+f"((c)[0]), "+f"((c)[1]), "+f"((c)[2]), "+f"((c)[3])              \
        : "r"((a)[0]), "r"((a)[1]), "r"((a)[2]), "r"((a)[3]), "r"(b0), "r"(b1))

// ---------------------------------------------------------------------------
// Merged prep: blocks [0,4096) do W rows; blocks [4096,12288) do x slices.
// ---------------------------------------------------------------------------
__global__ void prep_all(const float* __restrict__ x,
                         const float* __restrict__ W,
                         const float* __restrict__ wls,
                         float* __restrict__ jac_out) {
    extern __shared__ float sh[];    // [4096] row cache + [256] reduction
    if (blockIdx.x < 4096) {
        const int o = blockIdx.x;
        const int br = o >> 5;
        const int ncols = (br + 1) << 5;
        const int dstart = br << 5;
        const int kmax_tile = ((o >> 7) + 1) << 7;

        float* row = sh;
        float* red = sh + 4096;

        const float* wrow = W + (size_t)o * K_IN;
        __half* wh = g_wh + (size_t)o * K_IN;

        float ss = 0.f;
        for (int i = threadIdx.x; i < ncols; i += blockDim.x) {
            float w = wrow[i];
            float wm = (i >= dstart) ? expf(w) : w;
            row[i] = w;
            ss += wm * wm;
        }
        red[threadIdx.x] = ss;
        __syncthreads();
        #pragma unroll
        for (int s = 128; s > 0; s >>= 1) {
            if (threadIdx.x < s) red[threadIdx.x] += red[threadIdx.x + s];
            __syncthreads();
        }
        const float norm   = sqrtf(red[0]);
        const float lscale = wls[o];
        const float coef   = expf(lscale) / norm;
        const float logn   = logf(norm);

        for (int i = threadIdx.x; i < ncols; i += blockDim.x) {
            float w = row[i];
            float wm = (i >= dstart) ? expf(w) : w;
            wh[i] = __float2half_rn(coef * wm);
            if (i >= dstart)
                jac_out[(size_t)o * 32 + (i - dstart)] = lscale + w - logn;
        }
        const __half z = __float2half_rn(0.f);
        for (int i = ncols + threadIdx.x; i < kmax_tile; i += blockDim.x)
            wh[i] = z;
    } else {
        size_t i = ((size_t)(blockIdx.x - 4096) * blockDim.x + threadIdx.x) * 4;
        float4 v = *(const float4*)(x + i);
        __half h0 = __float2half_rn(v.x), h1 = __float2half_rn(v.y);
        __half h2 = __float2half_rn(v.z), h3 = __float2half_rn(v.w);
        *(__half2*)(&g_xh[i])     = __halves2half2(h0, h1);
        *(__half2*)(&g_xh[i + 2]) = __halves2half2(h2, h3);
    }
}

// ---------------------------------------------------------------------------
// fp16 GEMM: y = fp16(x) @ fp16(Wn)^T + bias.
// CTA tile 128x128, 8 warps (4m x 2n => 32x64 per warp), BK=64,
// 3-stage cp.async (96 KB), 2 CTAs/SM, one __syncthreads per chunk.
// Triangular: Kmax = 128*(nt+1).
// Schedule: tiles sorted desc by cost, T[j]: nt=31-j/16, mt=j%16.
//   bid <148   -> j = bid            (heaviest 148, wave-1 slot A)
//   bid <296   -> j = 511-(bid-148)  (lightest 148, wave-1 slot B; classic
//                                     placement puts bid & bid+148 on one SM,
//                                     so per-SM cost anti-correlates)
//   bid >=296  -> j = bid-148        (medium tiles, work-stolen as SMs free)
// ---------------------------------------------------------------------------
#define STAGE 32768
#define NSTAGE 3
#define SMEM_TOTAL (NSTAGE * STAGE)

__global__ __launch_bounds__(256, 2)
void gemm_mma(const float* __restrict__ bias, float* __restrict__ y) {
    extern __shared__ __align__(1024) char smem[];
    const uint32_t sb = smem_u32(smem);

    const int tid  = threadIdx.x;
    const int wid  = tid >> 5;
    const int lane = tid & 31;
    const int wm = wid >> 1;          // 0..3
    const int wn = wid & 1;           // 0..1

    const int bid = blockIdx.x;
    int j;
    if (bid < 148)      j = bid;
    else if (bid < 296) j = 511 - (bid - 148);
    else                j = bid - 148;
    const int nt = 31 - (j >> 4);
    const int mt = j & 15;
    const int n0 = nt << 7;
    const int m0 = mt << 7;
    const int NC = (nt + 1) << 1;     // K chunks of 64 (NC >= 2 always)

    const __half* gA = g_xh + (size_t)m0 * K_IN;
    const __half* gB = g_wh + (size_t)n0 * K_IN;

    float acc[2][8][4];
    #pragma unroll
    for (int i = 0; i < 2; i++)
        #pragma unroll
        for (int jj = 0; jj < 8; jj++)
            #pragma unroll
            for (int k = 0; k < 4; k++) acc[i][jj][k] = 0.f;

    auto load_stage = [&](int s, int c) {
        const uint32_t base = sb + s * STAGE;
        const int k0 = c << 6;
        #pragma unroll
        for (int i = 0; i < 4; i++) {
            const int idx = tid + (i << 8);   // 0..1023 chunk positions
            const int r = idx >> 3;
            const int ch = idx & 7;
            const size_t go = (size_t)r * K_IN + k0 + (ch << 3);
            const uint32_t so = (uint32_t)((r << 7) | ((ch ^ (r & 7)) << 4));
            cp16(base + so,         gA + go);
            cp16(base + 16384 + so, gB + go);
        }
    };

    // Prologue: chunks 0 and 1 (NC >= 2 always).
    load_stage(0, 0);
    CP_COMMIT();
    load_stage(1, 1);
    CP_COMMIT();

    int st = 2;   // stage for next load (chunk 2)
    for (int c = 0; c < NC; ++c) {
        CP_WAIT1();                        // chunk c's group complete
        __syncthreads();                   // all warps done with chunk c-1
        if (c + 2 < NC) load_stage(st, c + 2);
        CP_COMMIT();                       // empty group in the tail
        if (++st == NSTAGE) st = 0;

        const uint32_t base = sb + (c % NSTAGE) * STAGE;
        #pragma unroll
        for (int ks = 0; ks < 4; ks++) {
            uint32_t ah[2][4];
            #pragma unroll
            for (int mf = 0; mf < 2; mf++) {
                const int row = (wm << 5) + (mf << 4) + (lane & 15);
                const int ch = ((ks << 1) + (lane >> 4)) ^ (row & 7);
                LDM4(ah[mf], base + (row << 7) + (ch << 4));
            }
            #pragma unroll
            for (int ng = 0; ng < 4; ng++) {
                const int n = (wn << 6) + (ng << 4) + ((lane >> 4) << 3) + (lane & 7);
                const int ch = ((ks << 1) + ((lane >> 3) & 1)) ^ (n & 7);
                uint32_t bh[4];
                LDM4(bh, base + 16384 + (n << 7) + (ch << 4));
                #pragma unroll
                for (int mf = 0; mf < 2; mf++)
                    #pragma unroll
                    for (int h = 0; h < 2; h++)
                        MMAF16(acc[mf][(ng << 1) + h], ah[mf], bh[2 * h], bh[2 * h + 1]);
            }
        }
    }

    // Epilogue
    #pragma unroll
    for (int mf = 0; mf < 2; mf++) {
        const int r = m0 + (wm << 5) + (mf << 4) + (lane >> 2);
        #pragma unroll
        for (int nf = 0; nf < 8; nf++) {
            const int cc = n0 + (wn << 6) + (nf << 3) + ((lane & 3) << 1);
            const float b0 = __ldg(bias + cc);
            const float b1 = __ldg(bias + cc + 1);
            float2 v0 = { acc[mf][nf][0] + b0, acc[mf][nf][1] + b1 };
            float2 v1 = { acc[mf][nf][2] + b0, acc[mf][nf][3] + b1 };
            *(float2*)(y + (size_t)r * N_OUT + cc)       = v0;
            *(float2*)(y + (size_t)(r + 8) * N_OUT + cc) = v1;
        }
    }
}

// ---------------------------------------------------------------------------
extern "C" void kernel_launch(void* const* d_in, const int* in_sizes, int n_in,
                              void* d_out, int out_size) {
    const float* x    = (const float*)d_in[0];
    const float* W    = (const float*)d_in[1];
    const float* bias = (const float*)d_in[2];
    const float* wls  = (const float*)d_in[3];
    // masks (d_in[4], d_in[5]) deterministic; never read.

    float* y   = (float*)d_out;
    float* jac = y + (size_t)M_BATCH * N_OUT;

    cudaFuncSetAttribute(gemm_mma, cudaFuncAttributeMaxDynamicSharedMemorySize,
                         SMEM_TOTAL);

    prep_all<<<12288, 256, (4096 + 256) * sizeof(float)>>>(x, W, wls, jac);
    gemm_mma<<<512, 256, SMEM_TOTAL>>>(bias, y);
}

// round 10
// speedup vs baseline: 1.0659x; 1.0295x over previous
#include <cuda_runtime.h>
#include <cuda_fp16.h>
#include <math.h>
#include <stdint.h>

#define M_BATCH 2048
#define N_OUT   4096
#define K_IN    4096

// Persistent fp16 operands (module-load allocations; no runtime alloc).
__device__ __half g_xh[(size_t)M_BATCH * K_IN];   // fp16(x)
__device__ __half g_wh[(size_t)N_OUT * K_IN];     // fp16(Wn)

// ---------------------------------------------------------------------------
__device__ __forceinline__ uint32_t smem_u32(const void* p) {
    uint32_t a;
    asm("{ .reg .u64 t; cvta.to.shared.u64 t, %1; cvt.u32.u64 %0, t; }"
        : "=r"(a) : "l"(p));
    return a;
}
__device__ __forceinline__ void cp16(uint32_t s, const void* g) {
    asm volatile("cp.async.cg.shared.global [%0], [%1], 16;" :: "r"(s), "l"(g));
}
#define CP_COMMIT() asm volatile("cp.async.commit_group;" ::: "memory")
#define CP_WAIT1()  asm volatile("cp.async.wait_group 1;" ::: "memory")

#define LDM4(d, addr)                                                         \
    asm volatile("ldmatrix.sync.aligned.m8n8.x4.shared.b16 {%0,%1,%2,%3}, [%4];" \
        : "=r"((d)[0]), "=r"((d)[1]), "=r"((d)[2]), "=r"((d)[3]) : "r"(addr))

#define MMAF16(c, a, b0, b1)                                                  \
    asm volatile("mma.sync.aligned.m16n8k16.row.col.f32.f16.f16.f32 "         \
        "{%0,%1,%2,%3}, {%4,%5,%6,%7}, {%8,%9}, {%0,%1,%2,%3};"               \
        : "+f"((c)[0]), "+f"((c)[1]), "+f"((c)[2]), "+f"((c)[3])              \
        : "r"((a)[0]), "r"((a)[1]), "r"((a)[2]), "r"((a)[3]), "r"(b0), "r"(b1))

// ---------------------------------------------------------------------------
// Merged prep: blocks [0,4096) do W rows; blocks [4096,12288) do x slices.
// ---------------------------------------------------------------------------
__global__ void prep_all(const float* __restrict__ x,
                         const float* __restrict__ W,
                         const float* __restrict__ wls,
                         float* __restrict__ jac_out) {
    extern __shared__ float sh[];    // [4096] row cache + [256] reduction
    if (blockIdx.x < 4096) {
        const int o = blockIdx.x;
        const int br = o >> 5;
        const int ncols = (br + 1) << 5;
        const int dstart = br << 5;
        const int kmax_tile = ((o >> 7) + 1) << 7;

        float* row = sh;
        float* red = sh + 4096;

        const float* wrow = W + (size_t)o * K_IN;
        __half* wh = g_wh + (size_t)o * K_IN;

        float ss = 0.f;
        for (int i = threadIdx.x; i < ncols; i += blockDim.x) {
            float w = wrow[i];
            float wm = (i >= dstart) ? expf(w) : w;
            row[i] = w;
            ss += wm * wm;
        }
        red[threadIdx.x] = ss;
        __syncthreads();
        #pragma unroll
        for (int s = 128; s > 0; s >>= 1) {
            if (threadIdx.x < s) red[threadIdx.x] += red[threadIdx.x + s];
            __syncthreads();
        }
        const float norm   = sqrtf(red[0]);
        const float lscale = wls[o];
        const float coef   = expf(lscale) / norm;
        const float logn   = logf(norm);

        for (int i = threadIdx.x; i < ncols; i += blockDim.x) {
            float w = row[i];
            float wm = (i >= dstart) ? expf(w) : w;
            wh[i] = __float2half_rn(coef * wm);
            if (i >= dstart)
                jac_out[(size_t)o * 32 + (i - dstart)] = lscale + w - logn;
        }
        const __half z = __float2half_rn(0.f);
        for (int i = ncols + threadIdx.x; i < kmax_tile; i += blockDim.x)
            wh[i] = z;
    } else {
        size_t i = ((size_t)(blockIdx.x - 4096) * blockDim.x + threadIdx.x) * 4;
        float4 v = *(const float4*)(x + i);
        __half h0 = __float2half_rn(v.x), h1 = __float2half_rn(v.y);
        __half h2 = __float2half_rn(v.z), h3 = __float2half_rn(v.w);
        *(__half2*)(&g_xh[i])     = __halves2half2(h0, h1);
        *(__half2*)(&g_xh[i + 2]) = __halves2half2(h2, h3);
    }
}

// ---------------------------------------------------------------------------
// fp16 GEMM: y = fp16(x) @ fp16(Wn)^T + bias.
// CTA tile 128x128, 4 warps (2m x 2n => 64x64 per warp), 128 threads,
// BK=64, 3-stage cp.async (96 KB), 2 CTAs/SM, one __syncthreads per chunk.
// 64x64 warp tile cuts LDSM to 128 B/MMA (A x2, B x2 redundancy).
// Triangular: Kmax = 128*(nt+1).
// Schedule: sorted desc by cost, T[j]: nt=31-j/16, mt=j%16;
//   bid<148 -> j=bid; bid<296 -> j=511-(bid-148); else j=bid-148.
// Stage (32 KB): A @0 (128x64), B @16K. Swizzle: 16B-chunk ^= (row&7).
// ---------------------------------------------------------------------------
#define STAGE 32768
#define NSTAGE 3
#define SMEM_TOTAL (NSTAGE * STAGE)

__global__ __launch_bounds__(128, 2)
void gemm_mma(const float* __restrict__ bias, float* __restrict__ y) {
    extern __shared__ __align__(1024) char smem[];
    const uint32_t sb = smem_u32(smem);

    const int tid  = threadIdx.x;
    const int wid  = tid >> 5;
    const int lane = tid & 31;
    const int wm = wid >> 1;          // 0..1
    const int wn = wid & 1;           // 0..1

    const int bid = blockIdx.x;
    int j;
    if (bid < 148)      j = bid;
    else if (bid < 296) j = 511 - (bid - 148);
    else                j = bid - 148;
    const int nt = 31 - (j >> 4);
    const int mt = j & 15;
    const int n0 = nt << 7;
    const int m0 = mt << 7;
    const int NC = (nt + 1) << 1;     // K chunks of 64 (NC >= 2 always)

    const __half* gA = g_xh + (size_t)m0 * K_IN;
    const __half* gB = g_wh + (size_t)n0 * K_IN;

    float acc[4][8][4];
    #pragma unroll
    for (int i = 0; i < 4; i++)
        #pragma unroll
        for (int jj = 0; jj < 8; jj++)
            #pragma unroll
            for (int k = 0; k < 4; k++) acc[i][jj][k] = 0.f;

    auto load_stage = [&](int s, int c) {
        const uint32_t base = sb + s * STAGE;
        const int k0 = c << 6;
        #pragma unroll
        for (int i = 0; i < 8; i++) {
            const int idx = tid + (i << 7);   // 0..1023 chunk positions
            const int r = idx >> 3;
            const int ch = idx & 7;
            const size_t go = (size_t)r * K_IN + k0 + (ch << 3);
            const uint32_t so = (uint32_t)((r << 7) | ((ch ^ (r & 7)) << 4));
            cp16(base + so,         gA + go);
            cp16(base + 16384 + so, gB + go);
        }
    };

    // Prologue: chunks 0 and 1 (NC >= 2 always).
    load_stage(0, 0);
    CP_COMMIT();
    load_stage(1, 1);
    CP_COMMIT();

    int st = 2;   // stage slot for next prefetch (chunk 2)
    for (int c = 0; c < NC; ++c) {
        CP_WAIT1();                        // chunk c's group complete
        __syncthreads();                   // all warps done with chunk c-1
        if (c + 2 < NC) load_stage(st, c + 2);
        CP_COMMIT();                       // empty group in the tail
        if (++st == NSTAGE) st = 0;

        const uint32_t base = sb + (c % NSTAGE) * STAGE;
        #pragma unroll
        for (int ks = 0; ks < 4; ks++) {
            uint32_t ah[4][4];
            #pragma unroll
            for (int mf = 0; mf < 4; mf++) {
                const int row = (wm << 6) + (mf << 4) + (lane & 15);
                const int ch = ((ks << 1) + (lane >> 4)) ^ (row & 7);
                LDM4(ah[mf], base + (row << 7) + (ch << 4));
            }
            #pragma unroll
            for (int ng = 0; ng < 4; ng++) {
                const int n = (wn << 6) + (ng << 4) + ((lane >> 4) << 3) + (lane & 7);
                const int ch = ((ks << 1) + ((lane >> 3) & 1)) ^ (n & 7);
                uint32_t bh[4];
                LDM4(bh, base + 16384 + (n << 7) + (ch << 4));
                #pragma unroll
                for (int mf = 0; mf < 4; mf++)
                    #pragma unroll
                    for (int h = 0; h < 2; h++)
                        MMAF16(acc[mf][(ng << 1) + h], ah[mf], bh[2 * h], bh[2 * h + 1]);
            }
        }
    }

    // Epilogue
    #pragma unroll
    for (int mf = 0; mf < 4; mf++) {
        const int r = m0 + (wm << 6) + (mf << 4) + (lane >> 2);
        #pragma unroll
        for (int nf = 0; nf < 8; nf++) {
            const int cc = n0 + (wn << 6) + (nf << 3) + ((lane & 3) << 1);
            const float b0 = __ldg(bias + cc);
            const float b1 = __ldg(bias + cc + 1);
            float2 v0 = { acc[mf][nf][0] + b0, acc[mf][nf][1] + b1 };
            float2 v1 = { acc[mf][nf][2] + b0, acc[mf][nf][3] + b1 };
            *(float2*)(y + (size_t)r * N_OUT + cc)       = v0;
            *(float2*)(y + (size_t)(r + 8) * N_OUT + cc) = v1;
        }
    }
}

// ---------------------------------------------------------------------------
extern "C" void kernel_launch(void* const* d_in, const int* in_sizes, int n_in,
                              void* d_out, int out_size) {
    const float* x    = (const float*)d_in[0];
    const float* W    = (const float*)d_in[1];
    const float* bias = (const float*)d_in[2];
    const float* wls  = (const float*)d_in[3];
    // masks (d_in[4], d_in[5]) deterministic; never read.

    float* y   = (float*)d_out;
    float* jac = y + (size_t)M_BATCH * N_OUT;

    cudaFuncSetAttribute(gemm_mma, cudaFuncAttributeMaxDynamicSharedMemorySize,
                         SMEM_TOTAL);

    prep_all<<<12288, 256, (4096 + 256) * sizeof(float)>>>(x, W, wls, jac);
    gemm_mma<<<512, 128, SMEM_TOTAL>>>(bias, y);
}

// round 11
// speedup vs baseline: 1.1259x; 1.0563x over previous
#include <cuda_runtime.h>
#include <cuda_fp16.h>
#include <math.h>
#include <stdint.h>

#define M_BATCH 2048
#define N_OUT   4096
#define K_IN    4096

// Persistent fp16 operands (module-load allocations; no runtime alloc).
__device__ __half g_xh[(size_t)M_BATCH * K_IN];   // fp16(x)
__device__ __half g_wh[(size_t)N_OUT * K_IN];     // fp16(Wn)

// ---------------------------------------------------------------------------
__device__ __forceinline__ uint32_t smem_u32(const void* p) {
    uint32_t a;
    asm("{ .reg .u64 t; cvta.to.shared.u64 t, %1; cvt.u32.u64 %0, t; }"
        : "=r"(a) : "l"(p));
    return a;
}
__device__ __forceinline__ void cp16(uint32_t s, const void* g) {
    asm volatile("cp.async.cg.shared.global [%0], [%1], 16;" :: "r"(s), "l"(g));
}
#define CP_COMMIT() asm volatile("cp.async.commit_group;" ::: "memory")
#define CP_WAIT1()  asm volatile("cp.async.wait_group 1;" ::: "memory")

#define LDM4(d, addr)                                                         \
    asm volatile("ldmatrix.sync.aligned.m8n8.x4.shared.b16 {%0,%1,%2,%3}, [%4];" \
        : "=r"((d)[0]), "=r"((d)[1]), "=r"((d)[2]), "=r"((d)[3]) : "r"(addr))

#define MMAF16(c, a, b0, b1)                                                  \
    asm volatile("mma.sync.aligned.m16n8k16.row.col.f32.f16.f16.f32 "         \
        "{%0,%1,%2,%3}, {%4,%5,%6,%7}, {%8,%9}, {%0,%1,%2,%3};"               \
        : "+f"((c)[0]), "+f"((c)[1]), "+f"((c)[2]), "+f"((c)[3])              \
        : "r"((a)[0]), "r"((a)[1]), "r"((a)[2]), "r"((a)[3]), "r"(b0), "r"(b1))

// ---------------------------------------------------------------------------
// Merged prep: blocks [0,4096) do W rows; blocks [4096,12288) do x slices.
// ---------------------------------------------------------------------------
__global__ void prep_all(const float* __restrict__ x,
                         const float* __restrict__ W,
                         const float* __restrict__ wls,
                         float* __restrict__ jac_out) {
    extern __shared__ float sh[];    // [4096] row cache + [256] reduction
    if (blockIdx.x < 4096) {
        const int o = blockIdx.x;
        const int br = o >> 5;
        const int ncols = (br + 1) << 5;
        const int dstart = br << 5;
        const int kmax_tile = ((o >> 7) + 1) << 7;

        float* row = sh;
        float* red = sh + 4096;

        const float* wrow = W + (size_t)o * K_IN;
        __half* wh = g_wh + (size_t)o * K_IN;

        float ss = 0.f;
        for (int i = threadIdx.x; i < ncols; i += blockDim.x) {
            float w = wrow[i];
            float wm = (i >= dstart) ? expf(w) : w;
            row[i] = w;
            ss += wm * wm;
        }
        red[threadIdx.x] = ss;
        __syncthreads();
        #pragma unroll
        for (int s = 128; s > 0; s >>= 1) {
            if (threadIdx.x < s) red[threadIdx.x] += red[threadIdx.x + s];
            __syncthreads();
        }
        const float norm   = sqrtf(red[0]);
        const float lscale = wls[o];
        const float coef   = expf(lscale) / norm;
        const float logn   = logf(norm);

        for (int i = threadIdx.x; i < ncols; i += blockDim.x) {
            float w = row[i];
            float wm = (i >= dstart) ? expf(w) : w;
            wh[i] = __float2half_rn(coef * wm);
            if (i >= dstart)
                jac_out[(size_t)o * 32 + (i - dstart)] = lscale + w - logn;
        }
        const __half z = __float2half_rn(0.f);
        for (int i = ncols + threadIdx.x; i < kmax_tile; i += blockDim.x)
            wh[i] = z;
    } else {
        size_t i = ((size_t)(blockIdx.x - 4096) * blockDim.x + threadIdx.x) * 4;
        float4 v = *(const float4*)(x + i);
        __half h0 = __float2half_rn(v.x), h1 = __float2half_rn(v.y);
        __half h2 = __float2half_rn(v.z), h3 = __float2half_rn(v.w);
        *(__half2*)(&g_xh[i])     = __halves2half2(h0, h1);
        *(__half2*)(&g_xh[i + 2]) = __halves2half2(h2, h3);
    }
}

// ---------------------------------------------------------------------------
// Persistent fp16 GEMM: y = fp16(x) @ fp16(Wn)^T + bias.
// 296 CTAs (2/SM), 128 threads (2m x 2n warps => 64x64 tiles), CTA 128x128,
// BK=64, 3-stage cp.async (96 KB), one __syncthreads per chunk.
// Static schedule over cost-sorted tiles T[j] (nt=31-j/16, mt=j%16,
// NC=2(nt+1) = 64-2*(j>>4)):
//   slot s (=blockIdx.x) runs j=s, then j=591-s if 80<=s<=295.
//   -> slot loads: 56..64 chunks (flat); no second launch wave.
// Next tile's prologue loads are issued before the current epilogue so the
// pipeline refill hides behind the y-stores.
// ---------------------------------------------------------------------------
#define STAGE 32768
#define NSTAGE 3
#define SMEM_TOTAL (NSTAGE * STAGE)

__global__ __launch_bounds__(128, 2)
void gemm_mma(const float* __restrict__ bias, float* __restrict__ y) {
    extern __shared__ __align__(1024) char smem[];
    const uint32_t sb = smem_u32(smem);

    const int tid  = threadIdx.x;
    const int wid  = tid >> 5;
    const int lane = tid & 31;
    const int wm = wid >> 1;          // 0..1
    const int wn = wid & 1;           // 0..1

    const int s = blockIdx.x;         // persistent slot, 0..295
    const int ntiles = (s >= 80) ? 2 : 1;

    // Tile-0 setup + prologue (chunks 0,1 into stages 0,1).
    int j = s;
    int nt = 31 - (j >> 4);
    int mt = j & 15;
    int n0 = nt << 7;
    int m0 = mt << 7;
    int NC = (nt + 1) << 1;

    const __half* gA = g_xh + (size_t)m0 * K_IN;
    const __half* gB = g_wh + (size_t)n0 * K_IN;

    auto load_stage = [&](int st, int c) {
        const uint32_t base = sb + st * STAGE;
        const int k0 = c << 6;
        #pragma unroll
        for (int i = 0; i < 8; i++) {
            const int idx = tid + (i << 7);   // 0..1023 chunk positions
            const int r = idx >> 3;
            const int ch = idx & 7;
            const size_t go = (size_t)r * K_IN + k0 + (ch << 3);
            const uint32_t so = (uint32_t)((r << 7) | ((ch ^ (r & 7)) << 4));
            cp16(base + so,         gA + go);
            cp16(base + 16384 + so, gB + go);
        }
    };

    load_stage(0, 0);
    CP_COMMIT();
    load_stage(1, 1);
    CP_COMMIT();

    for (int t = 0; t < ntiles; t++) {
        float acc[4][8][4];
        #pragma unroll
        for (int i = 0; i < 4; i++)
            #pragma unroll
            for (int jj = 0; jj < 8; jj++)
                #pragma unroll
                for (int k = 0; k < 4; k++) acc[i][jj][k] = 0.f;

        int st = 2;   // stage slot for next prefetch (chunk 2)
        for (int c = 0; c < NC; ++c) {
            CP_WAIT1();                        // chunk c's group complete
            __syncthreads();                   // all warps done with chunk c-1
            if (c + 2 < NC) load_stage(st, c + 2);
            CP_COMMIT();                       // empty group in the tail
            if (++st == NSTAGE) st = 0;

            const uint32_t base = sb + (c % NSTAGE) * STAGE;
            #pragma unroll
            for (int ks = 0; ks < 4; ks++) {
                uint32_t ah[4][4];
                #pragma unroll
                for (int mf = 0; mf < 4; mf++) {
                    const int row = (wm << 6) + (mf << 4) + (lane & 15);
                    const int ch = ((ks << 1) + (lane >> 4)) ^ (row & 7);
                    LDM4(ah[mf], base + (row << 7) + (ch << 4));
                }
                #pragma unroll
                for (int ng = 0; ng < 4; ng++) {
                    const int n = (wn << 6) + (ng << 4) + ((lane >> 4) << 3) + (lane & 7);
                    const int ch = ((ks << 1) + ((lane >> 3) & 1)) ^ (n & 7);
                    uint32_t bh[4];
                    LDM4(bh, base + 16384 + (n << 7) + (ch << 4));
                    #pragma unroll
                    for (int mf = 0; mf < 4; mf++)
                        #pragma unroll
                        for (int h = 0; h < 2; h++)
                            MMAF16(acc[mf][(ng << 1) + h], ah[mf], bh[2 * h], bh[2 * h + 1]);
                }
            }
        }

        // Save output coords of this tile before switching.
        const int m0_out = m0, n0_out = n0;

        // Switch to next tile and issue its prologue BEFORE the epilogue,
        // so the refill hides behind the y-stores.
        __syncthreads();    // everyone done reading smem of this tile
        if (t + 1 < ntiles) {
            j = 591 - s;
            nt = 31 - (j >> 4);
            mt = j & 15;
            n0 = nt << 7;
            m0 = mt << 7;
            NC = (nt + 1) << 1;
            gA = g_xh + (size_t)m0 * K_IN;
            gB = g_wh + (size_t)n0 * K_IN;
            load_stage(0, 0);
            CP_COMMIT();
            load_stage(1, 1);
            CP_COMMIT();
        }

        // Epilogue for the finished tile.
        #pragma unroll
        for (int mf = 0; mf < 4; mf++) {
            const int r = m0_out + (wm << 6) + (mf << 4) + (lane >> 2);
            #pragma unroll
            for (int nf = 0; nf < 8; nf++) {
                const int cc = n0_out + (wn << 6) + (nf << 3) + ((lane & 3) << 1);
                const float b0 = __ldg(bias + cc);
                const float b1 = __ldg(bias + cc + 1);
                float2 v0 = { acc[mf][nf][0] + b0, acc[mf][nf][1] + b1 };
                float2 v1 = { acc[mf][nf][2] + b0, acc[mf][nf][3] + b1 };
                *(float2*)(y + (size_t)r * N_OUT + cc)       = v0;
                *(float2*)(y + (size_t)(r + 8) * N_OUT + cc) = v1;
            }
        }
    }
}

// ---------------------------------------------------------------------------
extern "C" void kernel_launch(void* const* d_in, const int* in_sizes, int n_in,
                              void* d_out, int out_size) {
    const float* x    = (const float*)d_in[0];
    const float* W    = (const float*)d_in[1];
    const float* bias = (const float*)d_in[2];
    const float* wls  = (const float*)d_in[3];
    // masks (d_in[4], d_in[5]) deterministic; never read.

    float* y   = (float*)d_out;
    float* jac = y + (size_t)M_BATCH * N_OUT;

    cudaFuncSetAttribute(gemm_mma, cudaFuncAttributeMaxDynamicSharedMemorySize,
                         SMEM_TOTAL);

    prep_all<<<12288, 256, (4096 + 256) * sizeof(float)>>>(x, W, wls, jac);
    gemm_mma<<<296, 128, SMEM_TOTAL>>>(bias, y);
}

// round 12
// speedup vs baseline: 1.1877x; 1.0549x over previous
#include <cuda_runtime.h>
#include <cuda_fp16.h>
#include <math.h>
#include <stdint.h>

#define M_BATCH 2048
#define N_OUT   4096
#define K_IN    4096

// Persistent fp16 operands (module-load allocations; no runtime alloc).
__device__ __half g_xh[(size_t)M_BATCH * K_IN];   // fp16(x)
__device__ __half g_wh[(size_t)N_OUT * K_IN];     // fp16(Wn)

// ---------------------------------------------------------------------------
__device__ __forceinline__ uint32_t smem_u32(const void* p) {
    uint32_t a;
    asm("{ .reg .u64 t; cvta.to.shared.u64 t, %1; cvt.u32.u64 %0, t; }"
        : "=r"(a) : "l"(p));
    return a;
}
__device__ __forceinline__ void cp16(uint32_t s, const void* g) {
    asm volatile("cp.async.cg.shared.global [%0], [%1], 16;" :: "r"(s), "l"(g));
}
#define CP_COMMIT() asm volatile("cp.async.commit_group;" ::: "memory")
#define CP_WAIT1()  asm volatile("cp.async.wait_group 1;" ::: "memory")

#define LDM4(d, addr)                                                         \
    asm volatile("ldmatrix.sync.aligned.m8n8.x4.shared.b16 {%0,%1,%2,%3}, [%4];" \
        : "=r"((d)[0]), "=r"((d)[1]), "=r"((d)[2]), "=r"((d)[3]) : "r"(addr))

#define MMAF16(c, a, b0, b1)                                                  \
    asm volatile("mma.sync.aligned.m16n8k16.row.col.f32.f16.f16.f32 "         \
        "{%0,%1,%2,%3}, {%4,%5,%6,%7}, {%8,%9}, {%0,%1,%2,%3};"               \
        : "+f"((c)[0]), "+f"((c)[1]), "+f"((c)[2]), "+f"((c)[3])              \
        : "r"((a)[0]), "r"((a)[1]), "r"((a)[2]), "r"((a)[3]), "r"(b0), "r"(b1))

__device__ __forceinline__ uint32_t pack2(float a, float b) {
    __half2 h = __halves2half2(__float2half_rn(a), __float2half_rn(b));
    return *(uint32_t*)&h;
}

// ---------------------------------------------------------------------------
// Merged prep, fully vectorized (8 elems/thread/step).
// Blocks [0,4096): W rows. Blocks [4096,8192): x slices.
// ---------------------------------------------------------------------------
__global__ void prep_all(const float* __restrict__ x,
                         const float* __restrict__ W,
                         const float* __restrict__ wls,
                         float* __restrict__ jac_out) {
    extern __shared__ float sh[];    // [4096] row cache + [256] reduction
    const int tid = threadIdx.x;
    if (blockIdx.x < 4096) {
        const int o = blockIdx.x;
        const int br = o >> 5;
        const int ncols = (br + 1) << 5;
        const int dstart = br << 5;
        const int kmax_tile = ((o >> 7) + 1) << 7;

        float* row = sh;
        float* red = sh + 4096;

        const float* wrow = W + (size_t)o * K_IN;
        __half* wh = g_wh + (size_t)o * K_IN;

        // Pass 1: vector-load row, cache in smem, accumulate |Wm|^2.
        float ss = 0.f;
        for (int base = tid * 8; base < ncols; base += 2048) {
            float4 a = *(const float4*)(wrow + base);
            float4 b = *(const float4*)(wrow + base + 4);
            *(float4*)(row + base)     = a;
            *(float4*)(row + base + 4) = b;
            float w[8] = { a.x, a.y, a.z, a.w, b.x, b.y, b.z, b.w };
            #pragma unroll
            for (int e = 0; e < 8; e++) {
                float wm = (base + e >= dstart) ? expf(w[e]) : w[e];
                ss += wm * wm;
            }
        }
        red[tid] = ss;
        __syncthreads();
        #pragma unroll
        for (int s = 128; s > 0; s >>= 1) {
            if (tid < s) red[tid] += red[tid + s];
            __syncthreads();
        }
        const float norm   = sqrtf(red[0]);
        const float lscale = wls[o];
        const float coef   = expf(lscale) / norm;
        const float logn   = logf(norm);

        // Pass 2: vector-write fp16 row + jac (closed form).
        for (int base = tid * 8; base < ncols; base += 2048) {
            float wn[8];
            #pragma unroll
            for (int e = 0; e < 8; e++) {
                float w = row[base + e];
                float wm = (base + e >= dstart) ? expf(w) : w;
                wn[e] = coef * wm;
                if (base + e >= dstart)
                    jac_out[(size_t)o * 32 + (base + e - dstart)] =
                        lscale + w - logn;
            }
            uint4 out = { pack2(wn[0], wn[1]), pack2(wn[2], wn[3]),
                          pack2(wn[4], wn[5]), pack2(wn[6], wn[7]) };
            *(uint4*)(wh + base) = out;
        }
        // Zero-pad to tile K bound (vectorized).
        const uint4 z4 = {0u, 0u, 0u, 0u};
        for (int base = ncols + tid * 8; base < kmax_tile; base += 2048)
            *(uint4*)(wh + base) = z4;
    } else {
        size_t i = ((size_t)(blockIdx.x - 4096) * blockDim.x + tid) * 8;
        float4 a = *(const float4*)(x + i);
        float4 b = *(const float4*)(x + i + 4);
        uint4 out = { pack2(a.x, a.y), pack2(a.z, a.w),
                      pack2(b.x, b.y), pack2(b.z, b.w) };
        *(uint4*)(&g_xh[i]) = out;
    }
}

// ---------------------------------------------------------------------------
// Persistent fp16 GEMM: y = fp16(x) @ fp16(Wn)^T + bias.
// 296 CTAs (2/SM), 128 threads (2m x 2n warps => 64x64 tiles), CTA 128x128,
// BK=64, 3-stage cp.async (96 KB), one __syncthreads per chunk.
// Static schedule over cost-sorted tiles T[j] (nt=31-j/16, mt=j%16):
//   slot s runs j=s, then j=591-s if 80<=s<=295 (flat 56..64 chunks/slot).
// Next tile's prologue is issued before the current epilogue.
// ---------------------------------------------------------------------------
#define STAGE 32768
#define NSTAGE 3
#define SMEM_TOTAL (NSTAGE * STAGE)

__global__ __launch_bounds__(128, 2)
void gemm_mma(const float* __restrict__ bias, float* __restrict__ y) {
    extern __shared__ __align__(1024) char smem[];
    const uint32_t sb = smem_u32(smem);

    const int tid  = threadIdx.x;
    const int wid  = tid >> 5;
    const int lane = tid & 31;
    const int wm = wid >> 1;          // 0..1
    const int wn = wid & 1;           // 0..1

    const int s = blockIdx.x;         // persistent slot, 0..295
    const int ntiles = (s >= 80) ? 2 : 1;

    int j = s;
    int nt = 31 - (j >> 4);
    int mt = j & 15;
    int n0 = nt << 7;
    int m0 = mt << 7;
    int NC = (nt + 1) << 1;

    const __half* gA = g_xh + (size_t)m0 * K_IN;
    const __half* gB = g_wh + (size_t)n0 * K_IN;

    auto load_stage = [&](int st, int c) {
        const uint32_t base = sb + st * STAGE;
        const int k0 = c << 6;
        #pragma unroll
        for (int i = 0; i < 8; i++) {
            const int idx = tid + (i << 7);   // 0..1023 chunk positions
            const int r = idx >> 3;
            const int ch = idx & 7;
            const size_t go = (size_t)r * K_IN + k0 + (ch << 3);
            const uint32_t so = (uint32_t)((r << 7) | ((ch ^ (r & 7)) << 4));
            cp16(base + so,         gA + go);
            cp16(base + 16384 + so, gB + go);
        }
    };

    load_stage(0, 0);
    CP_COMMIT();
    load_stage(1, 1);
    CP_COMMIT();

    for (int t = 0; t < ntiles; t++) {
        float acc[4][8][4];
        #pragma unroll
        for (int i = 0; i < 4; i++)
            #pragma unroll
            for (int jj = 0; jj < 8; jj++)
                #pragma unroll
                for (int k = 0; k < 4; k++) acc[i][jj][k] = 0.f;

        int st = 2;
        for (int c = 0; c < NC; ++c) {
            CP_WAIT1();
            __syncthreads();
            if (c + 2 < NC) load_stage(st, c + 2);
            CP_COMMIT();
            if (++st == NSTAGE) st = 0;

            const uint32_t base = sb + (c % NSTAGE) * STAGE;
            #pragma unroll
            for (int ks = 0; ks < 4; ks++) {
                uint32_t ah[4][4];
                #pragma unroll
                for (int mf = 0; mf < 4; mf++) {
                    const int row = (wm << 6) + (mf << 4) + (lane & 15);
                    const int ch = ((ks << 1) + (lane >> 4)) ^ (row & 7);
                    LDM4(ah[mf], base + (row << 7) + (ch << 4));
                }
                #pragma unroll
                for (int ng = 0; ng < 4; ng++) {
                    const int n = (wn << 6) + (ng << 4) + ((lane >> 4) << 3) + (lane & 7);
                    const int ch = ((ks << 1) + ((lane >> 3) & 1)) ^ (n & 7);
                    uint32_t bh[4];
                    LDM4(bh, base + 16384 + (n << 7) + (ch << 4));
                    #pragma unroll
                    for (int mf = 0; mf < 4; mf++)
                        #pragma unroll
                        for (int h = 0; h < 2; h++)
                            MMAF16(acc[mf][(ng << 1) + h], ah[mf], bh[2 * h], bh[2 * h + 1]);
                }
            }
        }

        const int m0_out = m0, n0_out = n0;

        __syncthreads();    // everyone done reading this tile's smem
        if (t + 1 < ntiles) {
            j = 591 - s;
            nt = 31 - (j >> 4);
            mt = j & 15;
            n0 = nt << 7;
            m0 = mt << 7;
            NC = (nt + 1) << 1;
            gA = g_xh + (size_t)m0 * K_IN;
            gB = g_wh + (size_t)n0 * K_IN;
            load_stage(0, 0);
            CP_COMMIT();
            load_stage(1, 1);
            CP_COMMIT();
        }

        #pragma unroll
        for (int mf = 0; mf < 4; mf++) {
            const int r = m0_out + (wm << 6) + (mf << 4) + (lane >> 2);
            #pragma unroll
            for (int nf = 0; nf < 8; nf++) {
                const int cc = n0_out + (wn << 6) + (nf << 3) + ((lane & 3) << 1);
                const float b0 = __ldg(bias + cc);
                const float b1 = __ldg(bias + cc + 1);
                float2 v0 = { acc[mf][nf][0] + b0, acc[mf][nf][1] + b1 };
                float2 v1 = { acc[mf][nf][2] + b0, acc[mf][nf][3] + b1 };
                *(float2*)(y + (size_t)r * N_OUT + cc)       = v0;
                *(float2*)(y + (size_t)(r + 8) * N_OUT + cc) = v1;
            }
        }
    }
}

// ---------------------------------------------------------------------------
extern "C" void kernel_launch(void* const* d_in, const int* in_sizes, int n_in,
                              void* d_out, int out_size) {
    const float* x    = (const float*)d_in[0];
    const float* W    = (const float*)d_in[1];
    const float* bias = (const float*)d_in[2];
    const float* wls  = (const float*)d_in[3];
    // masks (d_in[4], d_in[5]) deterministic; never read.

    float* y   = (float*)d_out;
    float* jac = y + (size_t)M_BATCH * N_OUT;

    cudaFuncSetAttribute(gemm_mma, cudaFuncAttributeMaxDynamicSharedMemorySize,
                         SMEM_TOTAL);

    prep_all<<<8192, 256, (4096 + 256) * sizeof(float)>>>(x, W, wls, jac);
    gemm_mma<<<296, 128, SMEM_TOTAL>>>(bias, y);
}